// round 15
// baseline (speedup 1.0000x reference)
#include <cuda_runtime.h>
#include <stdint.h>
#include <math.h>

#define WRANKS 4
#define NUM_HEADS 32
#define HEAD_SIZE 128
#define GKV 8              // kv heads
#define QPG 4              // query heads per kv head
#define BLOCK_SIZE 16
#define NUM_BLOCKS 1024
#define MAX_BLOCKS 32
#define MAX_CTX 512
#define NSEQ 32
#define NCHUNK 8
#define NPER (WRANKS * NCHUNK)                 // 32 partials per (seq, g)
#define NPART (NSEQ * GKV * NPER)              // 8192 partials
#define ATT_SCALE 0.08838834764831845f         // 1/sqrt(128)

#define PAGE_BYTES 65536                       // GKV*BLOCK_SIZE*HEAD_SIZE*4
#define RANK_BYTES ((size_t)NUM_BLOCKS * PAGE_BYTES)
#define GOFF_BYTES (BLOCK_SIZE * HEAD_SIZE * 4)  // 8192

// Partial-result scratch — __device__ globals (L2-resident working set).
__device__ float g_num[NPART][QPG][HEAD_SIZE]; // 16 MB
__device__ float g_m[NPART][QPG];
__device__ float g_e[NPART][QPG];
__device__ int   g_cnt[NSEQ * GKV];            // arrival counters (reset by last CTA)

__device__ __forceinline__ int pidx(int w, int s, int g, int c) {
    return ((w * NSEQ + s) * GKV + g) * NCHUNK + c;
}

// Merge two butterfly-reduction streams (1 SHFL per merge).
__device__ __forceinline__ float mergestep(float x, float y, int cond, int d) {
    const float keep = cond ? y : x;
    const float send = cond ? x : y;
    return keep + __shfl_xor_sync(0xFFFFFFFFu, send, d);
}

__device__ __forceinline__ uint64_t pack2(float p) {
    const uint32_t u = __float_as_uint(p);
    uint64_t r;
    asm("mov.b64 %0, {%1, %2};" : "=l"(r) : "r"(u), "r"(u));
    return r;
}
__device__ __forceinline__ void ffma2(uint64_t& acc, uint64_t a, uint64_t b) {
    asm("fma.rn.f32x2 %0, %1, %2, %0;" : "+l"(acc) : "l"(a), "l"(b));
}
__device__ __forceinline__ float2 unpack2(uint64_t v) {
    uint32_t lo, hi;
    asm("mov.b64 {%0, %1}, %2;" : "=r"(lo), "=r"(hi) : "l"(v));
    return make_float2(__uint_as_float(lo), __uint_as_float(hi));
}

// ---------------------------------------------------------------------------
// Fused single-pass kernel (max-free exp, m == 0 for live partials) +
// last-block cross-partial LSE merge.
// Chunk c owns pages {c, c+8, c+16, c+24} (strided, fine grain: mp <= 4).
// grid = (NSEQ*GKV, WRANKS, NCHUNK), block = 128 (4 warps).
// ---------------------------------------------------------------------------
__global__ __launch_bounds__(128, 8)
void dpa_fused(const float* __restrict__ query,
               const float* __restrict__ key_cache,
               const float* __restrict__ value_cache,
               const int*   __restrict__ block_tables,
               const int*   __restrict__ context_lens,
               float*       __restrict__ out)
{
    // floats: qs[0,512) | pbuf[512,640) ([4 warps][2][16]) | me[640,656) | red[656,2704)
    __shared__ float smem[2704];
    __shared__ int   bt_s[4];             // this chunk's (strided) pages
    __shared__ int   is_last_s;

    const int sg   = blockIdx.x;          // 0..255
    const int s    = sg >> 3;
    const int g    = sg & 7;
    const int w    = blockIdx.y;
    const int c    = blockIdx.z;          // 0..7
    const int tid  = threadIdx.x;
    const int lane = tid & 31;
    const int warp = tid >> 5;            // 0..3

    const int P   = pidx(w, s, g, c);
    const int ctx = context_lens[w * NSEQ + s];
    const int npt = (ctx + 15) >> 4;      // total live pages for this (w,s)

    if (c < npt) {
        const int mp       = ((npt - 1 - c) >> 3) + 1;       // my page count (1..4)
        const bool ownlast = (((npt - 1 - c) & 7) == 0);     // I own the partial page
        const int nloc     = ownlast ? ((mp - 1) * 16 + (ctx - ((npt - 1) << 4)))
                                     : (mp * 16);            // my live token count

        if (tid < 4)
            bt_s[tid] = block_tables[((size_t)w * NSEQ + s) * MAX_BLOCKS + c + 8 * tid];

        float* qs   = smem;           // [QPG][HEAD_SIZE], pre-scaled
        float* pbuf = smem + 512;     // [4 warps][2][16]
        float* me   = smem + 640;     // [4 warps][QPG] per-warp e
        float* red  = smem + 656;     // [4 warps][QPG][HEAD_SIZE]

        for (int i = tid; i < QPG * HEAD_SIZE; i += 128)
            qs[i] = query[(size_t)s * (NUM_HEADS * HEAD_SIZE)
                          + (size_t)g * (QPG * HEAD_SIZE) + i] * ATT_SCALE;
        __syncthreads();

        // warp covers tokens {warp, warp+4, warp+8, warp+12} of each page
        const char* kwp = (const char*)key_cache + (size_t)w * RANK_BYTES
                        + g * GOFF_BYTES + warp * 512 + lane * 16;
        const char* vwp = (const char*)value_cache + (size_t)w * RANK_BYTES
                        + g * GOFF_BYTES + warp * 512 + lane * 16;
        const float* qlp = qs + lane * 4;
        float* mypbuf = pbuf + warp * 32;
        const int cb0 = lane & 1, cb1 = lane & 2, cb2 = lane & 4, cb3 = lane & 8;
        const int myj = (lane >> 2) & 3;  // token slot for this lane's logit

        uint64_t accA[QPG], accB[QPG];
        #pragma unroll
        for (int h = 0; h < QPG; h++) { accA[h] = 0ull; accB[h] = 0ull; }
        float e_lane = 0.0f;

        for (int pg = 0; pg < mp; pg++) {
            const uint32_t po = ((uint32_t)bt_s[pg]) << 16;
            // 8 independent LDG.128: V loads cover the SHFL-reduce latency of K
            float4 k4[4];
            #pragma unroll
            for (int j = 0; j < 4; j++)
                k4[j] = *(const float4*)(kwp + po + j * 2048);   // token warp+4j
            ulonglong2 v4[4];
            #pragma unroll
            for (int j = 0; j < 4; j++)
                v4[j] = *(const ulonglong2*)(vwp + po + j * 2048);

            float p[4][QPG];
            #pragma unroll
            for (int j = 0; j < 4; j++) {
                #pragma unroll
                for (int h = 0; h < QPG; h++) {
                    const float4 q4 = *(const float4*)(qlp + h * HEAD_SIZE);
                    float x = k4[j].x * q4.x;
                    x = fmaf(k4[j].y, q4.y, x);
                    x = fmaf(k4[j].z, q4.z, x);
                    x = fmaf(k4[j].w, q4.w, x);
                    p[j][h] = x;
                }
            }
            // merged reduction of 16 series: head = lane bits 0-1, token = bits 2-3
            float mh[4];
            #pragma unroll
            for (int j = 0; j < 4; j++) {
                const float a = mergestep(p[j][0], p[j][1], cb0, 1);
                const float b = mergestep(p[j][2], p[j][3], cb0, 1);
                mh[j] = mergestep(a, b, cb1, 2);
            }
            const float t01 = mergestep(mh[0], mh[1], cb2, 4);
            const float t23 = mergestep(mh[2], mh[3], cb2, 4);
            float t = mergestep(t01, t23, cb3, 8);
            t += __shfl_xor_sync(0xFFFFFFFFu, t, 16);
            // lane holds logit(token warp+4*myj of page pg, head lane&3), halves identical

            const int tok = pg * 16 + warp + 4 * myj;
            const float pexp = (tok < nloc) ? __expf(t) : 0.0f;   // max-free exp (m == 0)
            e_lane += pexp;

            // exchange p within warp: [tok-slot][head] layout
            float* pb = mypbuf + ((pg & 1) << 4);
            if (lane < 16) pb[lane] = pexp;
            __syncwarp();

            #pragma unroll
            for (int j = 0; j < 4; j++) {
                const float4 pj = *(const float4*)(pb + j * 4);
                const float pja[4] = {pj.x, pj.y, pj.z, pj.w};
                #pragma unroll
                for (int h = 0; h < QPG; h++) {
                    const uint64_t pp = pack2(pja[h]);
                    ffma2(accA[h], v4[j].x, pp);
                    ffma2(accB[h], v4[j].y, pp);
                }
            }
        }

        // per-head e: sum lanes with same (lane&3); halves duplicate -> x0.5
        e_lane += __shfl_xor_sync(0xFFFFFFFFu, e_lane, 4);
        e_lane += __shfl_xor_sync(0xFFFFFFFFu, e_lane, 8);
        e_lane += __shfl_xor_sync(0xFFFFFFFFu, e_lane, 16);
        if (lane < QPG) me[warp * QPG + lane] = e_lane * 0.5f;

        float4* red4 = (float4*)red;   // [4 warps][QPG][32 float4]
        #pragma unroll
        for (int h = 0; h < QPG; h++) {
            const float2 a = unpack2(accA[h]);
            const float2 b = unpack2(accB[h]);
            red4[(warp * QPG + h) * 32 + lane] = make_float4(a.x, a.y, b.x, b.y);
        }
        __syncthreads();

        #pragma unroll
        for (int it = 0; it < 4; it++) {
            const int idx = tid + it * 128;     // (h, d)
            const int h = idx >> 7, d = idx & 127;
            float v = 0.0f;
            #pragma unroll
            for (int e = 0; e < 4; e++)
                v += red[(e * QPG + h) * 128 + d];
            g_num[P][h][d] = v;
        }
        if (tid < QPG) {
            g_m[P][tid] = 0.0f;      // max-free partial: m == 0
            g_e[P][tid] = me[tid] + me[QPG + tid] + me[2 * QPG + tid] + me[3 * QPG + tid];
        }
    } else {
        // Empty partial: merge weight is exactly 0; skip num writes.
        if (tid < QPG) { g_m[P][tid] = -1e30f; g_e[P][tid] = 0.0f; }
    }

    // ---- last-block arrival + fused reduce ---------------------------------
    __syncthreads();                 // all global writes of this CTA issued
    if (tid == 0) {
        __threadfence();             // release
        is_last_s = (atomicAdd(&g_cnt[sg], 1) == NPER - 1);
    }
    __syncthreads();
    if (!is_last_s) return;

    __threadfence();                 // acquire

    float* sm = smem;                // [NPER][QPG] = 128
    float* se = smem + NPER * QPG;
    {
        // tid indexes (p, h) directly: p = tid>>2, h = tid&3 (128 threads, 128 pairs)
        const int p = tid >> 2, h = tid & 3;
        const int Pq = pidx(p >> 3, s, g, p & 7);   // p = w*8 + c
        sm[tid] = g_m[Pq][h];
        se[p * QPG + h] = g_e[Pq][h];
    }
    __syncthreads();

    #pragma unroll
    for (int it = 0; it < 4; it++) {
        const int idx = tid + it * 128;     // (h, d)
        const int h = idx >> 7, d = idx & 127;
        float gmax = -1e30f;
        #pragma unroll
        for (int p = 0; p < NPER; p++)
            gmax = fmaxf(gmax, sm[p * QPG + h]);
        float den = 0.0f, val = 0.0f;
        #pragma unroll
        for (int p = 0; p < NPER; p++) {
            const float wgt = __expf(sm[p * QPG + h] - gmax);
            const int Pq = pidx(p >> 3, s, g, p & 7);
            den = fmaf(se[p * QPG + h], wgt, den);
            val = fmaf(g_num[Pq][h][d], wgt, val);
        }
        out[(size_t)sg * (QPG * HEAD_SIZE) + h * HEAD_SIZE + d] = val / den;
    }

    if (tid == 0) g_cnt[sg] = 0;
}

extern "C" void kernel_launch(void* const* d_in, const int* in_sizes, int n_in,
                              void* d_out, int out_size)
{
    const float* query        = (const float*)d_in[0];
    const float* key_cache    = (const float*)d_in[1];
    const float* value_cache  = (const float*)d_in[2];
    const int*   block_tables = (const int*)d_in[3];
    const int*   context_lens = (const int*)d_in[4];
    float*       out          = (float*)d_out;

    dim3 grid(NSEQ * GKV, WRANKS, NCHUNK);
    dpa_fused<<<grid, 128>>>(query, key_cache, value_cache,
                             block_tables, context_lens, out);
}

// round 16
// speedup vs baseline: 1.1315x; 1.1315x over previous
#include <cuda_runtime.h>
#include <stdint.h>
#include <math.h>

#define WRANKS 4
#define NUM_HEADS 32
#define HEAD_SIZE 128
#define GKV 8              // kv heads
#define QPG 4              // query heads per kv head
#define BLOCK_SIZE 16
#define NUM_BLOCKS 1024
#define MAX_BLOCKS 32
#define MAX_CTX 512
#define NSEQ 32
#define NCHUNK 4
#define NPER (WRANKS * NCHUNK)                 // 16 partials per (seq, g)
#define NPART (NSEQ * GKV * NPER)              // 4096 partials
#define ATT_SCALE 0.08838834764831845f         // 1/sqrt(128)

#define PAGE_BYTES 65536                       // GKV*BLOCK_SIZE*HEAD_SIZE*4
#define RANK_BYTES ((size_t)NUM_BLOCKS * PAGE_BYTES)
#define GOFF_BYTES (BLOCK_SIZE * HEAD_SIZE * 4)  // 8192

// Partial-result scratch — __device__ globals.
__device__ float g_num[NPART][QPG][HEAD_SIZE]; // 8 MB
__device__ float g_m[NPART][QPG];
__device__ float g_e[NPART][QPG];
__device__ int   g_cnt[NSEQ * GKV];            // arrival counters (reset by last CTA)

__device__ __forceinline__ int pidx(int w, int s, int g, int c) {
    return ((w * NSEQ + s) * GKV + g) * NCHUNK + c;
}

// Merge two butterfly-reduction streams (1 SHFL per merge).
__device__ __forceinline__ float mergestep(float x, float y, int cond, int d) {
    const float keep = cond ? y : x;
    const float send = cond ? x : y;
    return keep + __shfl_xor_sync(0xFFFFFFFFu, send, d);
}

__device__ __forceinline__ uint64_t pack2(float p) {
    const uint32_t u = __float_as_uint(p);
    uint64_t r;
    asm("mov.b64 %0, {%1, %2};" : "=l"(r) : "r"(u), "r"(u));
    return r;
}
__device__ __forceinline__ void ffma2(uint64_t& acc, uint64_t a, uint64_t b) {
    asm("fma.rn.f32x2 %0, %1, %2, %0;" : "+l"(acc) : "l"(a), "l"(b));
}
__device__ __forceinline__ float2 unpack2(uint64_t v) {
    uint32_t lo, hi;
    asm("mov.b64 {%0, %1}, %2;" : "=r"(lo), "=r"(hi) : "l"(v));
    return make_float2(__uint_as_float(lo), __uint_as_float(hi));
}

__device__ __forceinline__ uint32_t smem_u32(const void* p) {
    uint32_t a;
    asm("{ .reg .u64 t; cvta.to.shared.u64 t, %1; cvt.u32.u64 %0, t; }"
        : "=r"(a) : "l"(p));
    return a;
}
__device__ __forceinline__ void cp_async16(uint32_t dst, const void* src) {
    asm volatile("cp.async.cg.shared.global [%0], [%1], 16;"
                 :: "r"(dst), "l"(src));
}
#define CP_COMMIT() asm volatile("cp.async.commit_group;")
#define CP_WAIT1()  asm volatile("cp.async.wait_group 1;")

// ---------------------------------------------------------------------------
// Fused kernel: two-phase partial attention with cp.async-staged K/V pages +
// last-block cross-partial LSE merge.
// Chunk c owns pages {c, c+4, c+8, ...} (strided) for load balance.
// grid = (NSEQ*GKV, WRANKS, NCHUNK), block = 128 (4 warps), 10 CTAs/SM.
// ---------------------------------------------------------------------------
__global__ __launch_bounds__(128, 10)
void dpa_fused(const float* __restrict__ query,
               const float* __restrict__ key_cache,
               const float* __restrict__ value_cache,
               const int*   __restrict__ block_tables,
               const int*   __restrict__ context_lens,
               float*       __restrict__ out)
{
    // floats: stage[0,4096) (2 x 8KB page buffers) | qs[4096,4608)
    //         logits[4608,5120)  ; red[2048) aliases stage
    __shared__ float smem[5120];
    __shared__ int   bt_s[8];             // this chunk's (strided) pages
    __shared__ float m_s[QPG], e_s[QPG];
    __shared__ int   is_last_s;

    const int sg   = blockIdx.x;          // 0..255
    const int s    = sg >> 3;
    const int g    = sg & 7;
    const int w    = blockIdx.y;
    const int c    = blockIdx.z;
    const int tid  = threadIdx.x;
    const int lane = tid & 31;
    const int warp = tid >> 5;            // 0..3

    const int P   = pidx(w, s, g, c);
    const int ctx = context_lens[w * NSEQ + s];
    const int npt = (ctx + 15) >> 4;      // total live pages for this (w,s)

    if (c < npt) {
        const int mp       = ((npt - 1 - c) >> 2) + 1;       // my page count (1..8)
        const bool ownlast = (((npt - 1 - c) & 3) == 0);     // I own the partial page
        const int nloc     = ownlast ? ((mp - 1) * 16 + (ctx - ((npt - 1) << 4)))
                                     : (mp * 16);            // my live token count

        if (tid < 8)
            bt_s[tid] = block_tables[((size_t)w * NSEQ + s) * MAX_BLOCKS + c + 4 * tid];

        float* stagebuf = smem;        // [2][2048] floats
        float* qs       = smem + 4096; // [QPG][HEAD_SIZE], pre-scaled
        float* logits   = smem + 4608; // [128][QPG]
        float* red      = smem;        // aliases stage (used after staging done)

        for (int i = tid; i < QPG * HEAD_SIZE; i += 128)
            qs[i] = query[(size_t)s * (NUM_HEADS * HEAD_SIZE)
                          + (size_t)g * (QPG * HEAD_SIZE) + i] * ATT_SCALE;
        __syncthreads();               // bt_s + qs visible

        const uint32_t st_u32 = smem_u32(stagebuf);
        const char* gk = (const char*)key_cache + (size_t)w * RANK_BYTES
                       + g * GOFF_BYTES;                      // + (page<<16)
        const char* gv = (const char*)value_cache + (size_t)w * RANK_BYTES
                       + g * GOFF_BYTES;
        const float* qlp = qs + lane * 4;
        const int cb0 = lane & 1, cb1 = lane & 2, cb2 = lane & 4, cb3 = lane & 8;

        // ---- stage helper: whole CTA copies one 8KB page -------------------
        #define STAGE(buf, gbase, pg)                                          \
            do {                                                               \
                const char* _src = (gbase) + (((uint32_t)bt_s[(pg)]) << 16)    \
                                 + tid * 16;                                   \
                const uint32_t _dst = st_u32 + ((buf) << 13) + tid * 16;       \
                _Pragma("unroll")                                              \
                for (int _i = 0; _i < 4; _i++)                                 \
                    cp_async16(_dst + _i * 2048, _src + _i * 2048);            \
            } while (0)

        // ---- QK phase: pipelined K pages -----------------------------------
        STAGE(0, gk, 0);
        CP_COMMIT();
        for (int pg = 0; pg < mp; pg++) {
            if (pg + 1 < mp) STAGE((pg + 1) & 1, gk, pg + 1);
            CP_COMMIT();
            CP_WAIT1();
            __syncthreads();           // page pg resident for all warps

            const float* kb = stagebuf + ((pg & 1) << 11);
            float4 k4[4];
            #pragma unroll
            for (int j = 0; j < 4; j++)
                k4[j] = *(const float4*)(kb + (warp + 4 * j) * 128 + lane * 4);

            float p[4][QPG];
            #pragma unroll
            for (int j = 0; j < 4; j++) {
                #pragma unroll
                for (int h = 0; h < QPG; h++) {
                    const float4 q4 = *(const float4*)(qlp + h * HEAD_SIZE);
                    float x = k4[j].x * q4.x;
                    x = fmaf(k4[j].y, q4.y, x);
                    x = fmaf(k4[j].z, q4.z, x);
                    x = fmaf(k4[j].w, q4.w, x);
                    p[j][h] = x;
                }
            }
            // merged reduction of 16 series: head = lane bits 0-1, token = bits 2-3
            float mh[4];
            #pragma unroll
            for (int j = 0; j < 4; j++) {
                const float a = mergestep(p[j][0], p[j][1], cb0, 1);
                const float b = mergestep(p[j][2], p[j][3], cb0, 1);
                mh[j] = mergestep(a, b, cb1, 2);
            }
            const float t01 = mergestep(mh[0], mh[1], cb2, 4);
            const float t23 = mergestep(mh[2], mh[3], cb2, 4);
            float t = mergestep(t01, t23, cb3, 8);
            t += __shfl_xor_sync(0xFFFFFFFFu, t, 16);
            if (lane < 16) {
                const int tok = pg * 16 + warp + ((lane >> 2) << 2);
                logits[tok * QPG + (lane & 3)] = t;
            }
            __syncthreads();           // all reads of this buffer done
        }

        // prefetch V page 0 — its latency hides under the softmax pass
        STAGE(0, gv, 0);
        CP_COMMIT();

        // ---- softmax (one warp per head), tail zero-fill folded in ---------
        {
            const int h = warp;
            float mx = -1e30f;
            for (int t = lane; t < nloc; t += 32)
                mx = fmaxf(mx, logits[t * QPG + h]);
            #pragma unroll
            for (int off = 16; off; off >>= 1)
                mx = fmaxf(mx, __shfl_xor_sync(0xFFFFFFFFu, mx, off));
            float sum = 0.0f;
            for (int t = lane; t < nloc; t += 32) {
                const float p = __expf(logits[t * QPG + h] - mx);
                logits[t * QPG + h] = p;
                sum += p;
            }
            #pragma unroll
            for (int off = 16; off; off >>= 1)
                sum += __shfl_xor_sync(0xFFFFFFFFu, sum, off);
            if (lane == 0) { m_s[h] = mx; e_s[h] = sum; }
            for (int t = nloc + lane; t < mp * 16; t += 32)
                logits[t * QPG + h] = 0.0f;
        }
        __syncthreads();

        // ---- PV phase: pipelined V pages, packed f32x2 FMAs ----------------
        uint64_t pvA[QPG], pvB[QPG];
        #pragma unroll
        for (int h = 0; h < QPG; h++) { pvA[h] = 0ull; pvB[h] = 0ull; }

        for (int pg = 0; pg < mp; pg++) {
            if (pg + 1 < mp) STAGE((pg + 1) & 1, gv, pg + 1);
            CP_COMMIT();
            CP_WAIT1();
            __syncthreads();

            const float* vb = stagebuf + ((pg & 1) << 11);
            ulonglong2 v4[4];
            #pragma unroll
            for (int j = 0; j < 4; j++)
                v4[j] = *(const ulonglong2*)(vb + (warp + 4 * j) * 128 + lane * 4);
            #pragma unroll
            for (int j = 0; j < 4; j++) {
                const float4 pj = *(const float4*)(logits + (pg * 16 + warp + 4 * j) * QPG);
                const float pja[4] = {pj.x, pj.y, pj.z, pj.w};
                #pragma unroll
                for (int h = 0; h < QPG; h++) {
                    const uint64_t pp = pack2(pja[h]);
                    ffma2(pvA[h], v4[j].x, pp);
                    ffma2(pvB[h], v4[j].y, pp);
                }
            }
            __syncthreads();
        }

        // ---- cross-warp (4-way) reduction, write partials ------------------
        float4* red4 = (float4*)red;   // [4 warps][QPG][32 float4] (aliases stage)
        #pragma unroll
        for (int h = 0; h < QPG; h++) {
            const float2 a = unpack2(pvA[h]);
            const float2 b = unpack2(pvB[h]);
            red4[(warp * QPG + h) * 32 + lane] = make_float4(a.x, a.y, b.x, b.y);
        }
        __syncthreads();

        #pragma unroll
        for (int it = 0; it < 4; it++) {
            const int idx = tid + it * 128;     // (h, d)
            const int h = idx >> 7, d = idx & 127;
            float v = 0.0f;
            #pragma unroll
            for (int e = 0; e < 4; e++)
                v += red[(e * QPG + h) * 128 + d];
            g_num[P][h][d] = v;
        }
        if (tid < QPG) { g_m[P][tid] = m_s[tid]; g_e[P][tid] = e_s[tid]; }
    } else {
        // Empty partial: merge weight is exactly 0; skip num writes.
        if (tid < QPG) { g_m[P][tid] = -1e30f; g_e[P][tid] = 0.0f; }
    }

    // ---- last-block arrival + fused reduce ---------------------------------
    __syncthreads();                 // all global writes of this CTA issued
    if (tid == 0) {
        __threadfence();             // release
        is_last_s = (atomicAdd(&g_cnt[sg], 1) == NPER - 1);
    }
    __syncthreads();
    if (!is_last_s) return;

    __threadfence();                 // acquire

    float* sm = smem;                // [NPER][QPG]
    float* se = smem + NPER * QPG;
    if (tid < NPER * QPG) {
        const int p = tid >> 2, h = tid & 3;
        const int Pq = pidx(p >> 2, s, g, p & 3);   // p = w*4 + c
        sm[tid] = g_m[Pq][h];
        se[p * QPG + h] = g_e[Pq][h];
    }
    __syncthreads();

    #pragma unroll
    for (int it = 0; it < 4; it++) {
        const int idx = tid + it * 128;     // (h, d)
        const int h = idx >> 7, d = idx & 127;
        float gmax = -1e30f;
        #pragma unroll
        for (int p = 0; p < NPER; p++)
            gmax = fmaxf(gmax, sm[p * QPG + h]);
        float den = 0.0f, val = 0.0f;
        #pragma unroll
        for (int p = 0; p < NPER; p++) {
            const float wgt = __expf(sm[p * QPG + h] - gmax);
            const int Pq = pidx(p >> 2, s, g, p & 3);
            den = fmaf(se[p * QPG + h], wgt, den);
            val = fmaf(g_num[Pq][h][d], wgt, val);
        }
        out[(size_t)sg * (QPG * HEAD_SIZE) + h * HEAD_SIZE + d] = val / den;
    }

    if (tid == 0) g_cnt[sg] = 0;
}

extern "C" void kernel_launch(void* const* d_in, const int* in_sizes, int n_in,
                              void* d_out, int out_size)
{
    const float* query        = (const float*)d_in[0];
    const float* key_cache    = (const float*)d_in[1];
    const float* value_cache  = (const float*)d_in[2];
    const int*   block_tables = (const int*)d_in[3];
    const int*   context_lens = (const int*)d_in[4];
    float*       out          = (float*)d_out;

    dim3 grid(NSEQ * GKV, WRANKS, NCHUNK);
    dpa_fused<<<grid, 128>>>(query, key_cache, value_cache,
                             block_tables, context_lens, out);
}